// round 3
// baseline (speedup 1.0000x reference)
#include <cuda_runtime.h>
#include <cuda_bf16.h>

#define NNODES 50000
#define F 128
#define EMAX 800000
#define NEG 0.2f

// ---------------- scratch (no allocation allowed) ----------------
__device__ int   g_deg[NNODES];
__device__ int   g_cur[NNODES];
__device__ int   g_rowstart[NNODES + 1];
__device__ int   g_csr[EMAX];
__device__ int   g_is64;           // 1 if edge buffer is int64 little-endian pairs
__device__ float g_xl[NNODES * F];
__device__ float g_xr[NNODES * F];
__device__ float g_h[NNODES * F];

// ---------------- f32x2 packed helpers (sm_103a) ----------------
__device__ __forceinline__ unsigned long long pack2(float x) {
    unsigned long long r;
    asm("mov.b64 %0, {%1, %1};" : "=l"(r) : "f"(x));
    return r;
}
__device__ __forceinline__ void ffma2(unsigned long long& d,
                                      unsigned long long a,
                                      unsigned long long b) {
    asm("fma.rn.f32x2 %0, %1, %2, %0;" : "+l"(d) : "l"(a), "l"(b));
}
__device__ __forceinline__ float2 unpack2(unsigned long long v) {
    float2 u;
    asm("mov.b64 {%0, %1}, %2;" : "=f"(u.x), "=f"(u.y) : "l"(v));
    return u;
}

// ---------------- edge buffer layout detection ----------------
// If the staged buffer is raw int64 bytes viewed as int32, every odd int32
// position in the first few edges is a zero high-word. Plain int32 data has
// ~0 probability of 8 consecutive odd positions all being zero.
__global__ void k_detect(const int* __restrict__ ei32) {
    int z = 0;
#pragma unroll
    for (int i = 0; i < 8; i++) z |= ei32[2 * i + 1];
    g_is64 = (z == 0) ? 1 : 0;
}

__device__ __forceinline__ int edge_val(const int* __restrict__ ei32, int idx) {
    return g_is64 ? ei32[2 * idx] : ei32[idx];
}

// ---------------- CSR construction (guarded: invalid edges dropped) ----------------
__global__ void k_zero() {
    int i = blockIdx.x * blockDim.x + threadIdx.x;
    if (i < NNODES) { g_deg[i] = 0; g_cur[i] = 0; }
}

__global__ void k_count(const int* __restrict__ ei32, int E) {
    int e = blockIdx.x * blockDim.x + threadIdx.x;
    if (e >= E) return;
    int s = edge_val(ei32, e);
    int d = edge_val(ei32, E + e);
    if (s >= 0 && s < NNODES && d >= 0 && d < NNODES) atomicAdd(&g_deg[d], 1);
}

__global__ void k_scan(int n) {
    __shared__ int s[1024];
    __shared__ int carry_s;
    int t = threadIdx.x;
    if (t == 0) carry_s = 0;
    __syncthreads();
    for (int base = 0; base < n; base += 1024) {
        int idx = base + t;
        int v = (idx < n) ? g_deg[idx] : 0;
        s[t] = v;
        __syncthreads();
        for (int off = 1; off < 1024; off <<= 1) {
            int add = (t >= off) ? s[t - off] : 0;
            __syncthreads();
            s[t] += add;
            __syncthreads();
        }
        int incl = s[t];
        if (idx < n) g_rowstart[idx] = carry_s + incl - v;
        __syncthreads();
        if (t == 1023) carry_s += s[1023];
        __syncthreads();
    }
    if (t == 0) g_rowstart[n] = carry_s;
}

__global__ void k_fill(const int* __restrict__ ei32, int E) {
    int e = blockIdx.x * blockDim.x + threadIdx.x;
    if (e >= E) return;
    int s = edge_val(ei32, e);
    int d = edge_val(ei32, E + e);
    if (s < 0 || s >= NNODES || d < 0 || d >= NNODES) return;
    int pos = g_rowstart[d] + atomicAdd(&g_cur[d], 1);
    if (pos >= 0 && pos < EMAX) g_csr[pos] = s;
}

// ---------------- GEMM: C[nrows,128] = A[nrows,128] @ W[128,128] ----------------
#define BM 128
#define BN 128
#define BK 32
#define XPAD 36

template <int A_EXT, int DSTSEL>
__global__ __launch_bounds__(256) void k_gemm(const float* __restrict__ Aext,
                                              const float* __restrict__ W,
                                              int nrows) {
    const float* A = A_EXT ? Aext : (const float*)g_h;
    float*       C = DSTSEL ? g_xr : g_xl;

    __shared__ float xs[BM][XPAD];   // [m][k] (padded; row stride 144B, 16B-aligned)
    __shared__ float ws[BK][BN];

    int t  = threadIdx.x;
    int tx = t & 15;      // col group: cols tx*8 .. tx*8+7
    int ty = t >> 4;      // row group: rows ty*8 .. ty*8+7
    int row0 = blockIdx.x * BM;

    unsigned long long acc[8][4];
#pragma unroll
    for (int i = 0; i < 8; i++)
#pragma unroll
        for (int j = 0; j < 4; j++) acc[i][j] = 0ULL;

    for (int k0 = 0; k0 < F; k0 += BK) {
#pragma unroll
        for (int i = 0; i < 4; i++) {
            int f  = t + i * 256;
            int r  = f >> 3;
            int c4 = f & 7;
            float4 v = make_float4(0.f, 0.f, 0.f, 0.f);
            int gr = row0 + r;
            if (gr < nrows) v = *(const float4*)(A + gr * F + k0 + c4 * 4);
            *(float4*)&xs[r][c4 * 4] = v;
        }
#pragma unroll
        for (int i = 0; i < 4; i++) {
            int f  = t + i * 256;
            int r  = f >> 5;
            int c4 = f & 31;
            *(float4*)&ws[r][c4 * 4] = *(const float4*)(W + (k0 + r) * F + c4 * 4);
        }
        __syncthreads();

#pragma unroll
        for (int kk = 0; kk < BK; kk++) {
            unsigned long long xx[8];
#pragma unroll
            for (int i = 0; i < 8; i++) xx[i] = pack2(xs[ty * 8 + i][kk]);
            unsigned long long wv[4];
            const unsigned long long* wp =
                (const unsigned long long*)&ws[kk][tx * 8];
#pragma unroll
            for (int j = 0; j < 4; j++) wv[j] = wp[j];
#pragma unroll
            for (int i = 0; i < 8; i++)
#pragma unroll
                for (int j = 0; j < 4; j++) ffma2(acc[i][j], xx[i], wv[j]);
        }
        __syncthreads();
    }

#pragma unroll
    for (int i = 0; i < 8; i++) {
        int gr = row0 + ty * 8 + i;
        if (gr < nrows) {
            float2* op = (float2*)(C + gr * F + tx * 8);
#pragma unroll
            for (int j = 0; j < 4; j++) op[j] = unpack2(acc[i][j]);
        }
    }
}

// ---------------- fused online-softmax aggregation ----------------
template <int RW, bool RELU, int OUT_EXT>
__global__ __launch_bounds__(256) void k_agg(const float* __restrict__ att,
                                             const float* __restrict__ bias,
                                             float* __restrict__ outext) {
    const float* xl = g_xl;
    const float* xr = g_xr;
    float* out = OUT_EXT ? outext : g_h;

    int gw   = (blockIdx.x * blockDim.x + threadIdx.x) >> 5;
    int lane = threadIdx.x & 31;
    if (gw >= NNODES) return;
    int i = gw;
    int c = lane * 4;

    float4 xr4 = *(const float4*)(xr + i * F + c);
    float4 a4  = *(const float4*)(att + c);
    float4 b4  = *(const float4*)(bias + c);

    float4 xc = *(const float4*)(xl + i * F + c);   // self loop

    auto alpha_of = [&](const float4& v) -> float {
        float e0 = v.x + xr4.x; e0 = e0 > 0.f ? e0 : NEG * e0;
        float e1 = v.y + xr4.y; e1 = e1 > 0.f ? e1 : NEG * e1;
        float e2 = v.z + xr4.z; e2 = e2 > 0.f ? e2 : NEG * e2;
        float e3 = v.w + xr4.w; e3 = e3 > 0.f ? e3 : NEG * e3;
        float p = a4.x * e0 + a4.y * e1 + a4.z * e2 + a4.w * e3;
#pragma unroll
        for (int o = 1; o < RW; o <<= 1)
            p += __shfl_xor_sync(0xffffffffu, p, o);
        return p;
    };

    float  m    = alpha_of(xc);
    float  dsum = 1.f;
    float4 acc  = xc;

    int beg = g_rowstart[i], end = g_rowstart[i + 1];
    float4 xn = make_float4(0.f, 0.f, 0.f, 0.f);
    if (beg < end) {
        int j = g_csr[beg];
        xn = *(const float4*)(xl + j * F + c);
    }
    for (int e = beg; e < end; e++) {
        float4 cur = xn;
        if (e + 1 < end) {
            int j2 = g_csr[e + 1];
            xn = *(const float4*)(xl + j2 * F + c);
        }
        float p  = alpha_of(cur);
        float mn = fmaxf(m, p);
        float corr = __expf(m - mn);
        float w    = __expf(p - mn);
        dsum = dsum * corr + w;
        acc.x = acc.x * corr + w * cur.x;
        acc.y = acc.y * corr + w * cur.y;
        acc.z = acc.z * corr + w * cur.z;
        acc.w = acc.w * corr + w * cur.w;
        m = mn;
    }

    float inv = 1.0f / dsum;
    float4 o;
    o.x = acc.x * inv + b4.x;
    o.y = acc.y * inv + b4.y;
    o.z = acc.z * inv + b4.z;
    o.w = acc.w * inv + b4.w;
    if (RELU) {
        o.x = fmaxf(o.x, 0.f);
        o.y = fmaxf(o.y, 0.f);
        o.z = fmaxf(o.z, 0.f);
        o.w = fmaxf(o.w, 0.f);
    }
    *(float4*)(out + i * F + c) = o;
}

// ---------------- launch (kernel launches ONLY — graph-capture safe) ----------------
extern "C" void kernel_launch(void* const* d_in, const int* in_sizes, int n_in,
                              void* d_out, int out_size) {
    const float* x    = (const float*)d_in[0];
    const int*   ei32 = (const int*)d_in[1];
    const float* Wl1  = (const float*)d_in[2];
    const float* Wr1  = (const float*)d_in[3];
    const float* att1 = (const float*)d_in[4];
    const float* b1   = (const float*)d_in[5];
    const float* Wl2  = (const float*)d_in[6];
    const float* Wr2  = (const float*)d_in[7];
    const float* att2 = (const float*)d_in[8];
    const float* b2   = (const float*)d_in[9];
    float*       out  = (float*)d_out;

    // Edge count: robust to the buffer being reported as int64 elements (2E),
    // converted int32 (2E), or raw int64 bytes viewed as int32 (4E).
    int cnt = in_sizes[1];
    int E   = (cnt / 2 > EMAX) ? cnt / 4 : cnt / 2;
    if (E > EMAX) E = EMAX;

    int eb = (E + 255) / 256;
    int gb = (NNODES + BM - 1) / BM;          // 391
    int ab = (NNODES * 32 + 255) / 256;       // 6250

    k_detect<<<1, 1>>>(ei32);
    k_zero<<<(NNODES + 255) / 256, 256>>>();
    k_count<<<eb, 256>>>(ei32, E);
    k_scan<<<1, 1024>>>(NNODES);
    k_fill<<<eb, 256>>>(ei32, E);

    // layer 1: xl = x@Wl1, xr = x@Wr1, h = agg+relu
    k_gemm<1, 0><<<gb, 256>>>(x, Wl1, NNODES);
    k_gemm<1, 1><<<gb, 256>>>(x, Wr1, NNODES);
    k_agg<8, true, 0><<<ab, 256>>>(att1, b1, out);

    // layer 2: xl = h@Wl2, xr = h@Wr2, out = agg
    k_gemm<0, 0><<<gb, 256>>>(nullptr, Wl2, NNODES);
    k_gemm<0, 1><<<gb, 256>>>(nullptr, Wr2, NNODES);
    k_agg<32, false, 1><<<ab, 256>>>(att2, b2, out);
}

// round 4
// speedup vs baseline: 1.1619x; 1.1619x over previous
#include <cuda_runtime.h>
#include <cuda_bf16.h>

#define NNODES 50000
#define F 128
#define EMAX 800000
#define NEG 0.2f
#define NB_SCAN ((NNODES + 1023) / 1024)   // 49

// ---------------- scratch (no allocation allowed) ----------------
__device__ int   g_deg[NNODES];
__device__ int   g_cur[NNODES];
__device__ int   g_rowstart[NNODES + 1];
__device__ int   g_bsum[64];
__device__ int   g_csr[EMAX];
__device__ int   g_is64;           // 1 if edge buffer is int64 little-endian pairs
__device__ float g_xl[NNODES * F];
__device__ float g_xr[NNODES * F];
__device__ float g_h[NNODES * F];

// ---------------- f32x2 packed helpers (sm_103a) ----------------
__device__ __forceinline__ unsigned long long pack2(float x) {
    unsigned long long r;
    asm("mov.b64 %0, {%1, %1};" : "=l"(r) : "f"(x));
    return r;
}
__device__ __forceinline__ void ffma2(unsigned long long& d,
                                      unsigned long long a,
                                      unsigned long long b) {
    asm("fma.rn.f32x2 %0, %1, %2, %0;" : "+l"(d) : "l"(a), "l"(b));
}
__device__ __forceinline__ float2 unpack2(unsigned long long v) {
    float2 u;
    asm("mov.b64 {%0, %1}, %2;" : "=f"(u.x), "=f"(u.y) : "l"(v));
    return u;
}

// ---------------- zero + edge layout detection (fused) ----------------
__global__ void k_zero(const int* __restrict__ ei32) {
    int i = blockIdx.x * blockDim.x + threadIdx.x;
    if (i < NNODES) { g_deg[i] = 0; g_cur[i] = 0; }
    if (i == 0) {
        int z = 0;
#pragma unroll
        for (int k = 0; k < 8; k++) z |= ei32[2 * k + 1];
        g_is64 = (z == 0) ? 1 : 0;
    }
}

__device__ __forceinline__ int edge_val(const int* __restrict__ ei32, int idx) {
    return g_is64 ? ei32[2 * idx] : ei32[idx];
}

// ---------------- CSR construction ----------------
__global__ void k_count(const int* __restrict__ ei32, int E) {
    int e = blockIdx.x * blockDim.x + threadIdx.x;
    if (e >= E) return;
    int s = edge_val(ei32, e);
    int d = edge_val(ei32, E + e);
    if (s >= 0 && s < NNODES && d >= 0 && d < NNODES) atomicAdd(&g_deg[d], 1);
}

// multi-block scan, stage A: per-1024-chunk exclusive scan via warp shuffles
__global__ __launch_bounds__(1024) void k_scanA(int n) {
    __shared__ int wsum[32];
    int b = blockIdx.x, t = threadIdx.x;
    int lane = t & 31, w = t >> 5;
    int idx = b * 1024 + t;
    int v = (idx < n) ? g_deg[idx] : 0;
    int s = v;
#pragma unroll
    for (int o = 1; o < 32; o <<= 1) {
        int u = __shfl_up_sync(0xffffffffu, s, o);
        if (lane >= o) s += u;
    }
    if (lane == 31) wsum[w] = s;
    __syncthreads();
    if (w == 0) {
        int ws = wsum[lane];
#pragma unroll
        for (int o = 1; o < 32; o <<= 1) {
            int u = __shfl_up_sync(0xffffffffu, ws, o);
            if (lane >= o) ws += u;
        }
        wsum[lane] = ws;
    }
    __syncthreads();
    int excl = s - v + (w > 0 ? wsum[w - 1] : 0);
    if (idx < n) g_rowstart[idx] = excl;
    if (t == 1023) g_bsum[b] = wsum[31];
}

// stage B: scan the (<=64) chunk totals; write grand total to rowstart[n]
__global__ void k_scanB(int nb, int n) {
    __shared__ int s[64];
    int t = threadIdx.x;
    int v = (t < nb) ? g_bsum[t] : 0;
    s[t] = v;
    __syncthreads();
#pragma unroll
    for (int off = 1; off < 64; off <<= 1) {
        int a = (t >= off) ? s[t - off] : 0;
        __syncthreads();
        s[t] += a;
        __syncthreads();
    }
    if (t < nb) g_bsum[t] = s[t] - v;   // exclusive
    if (t == 63) g_rowstart[n] = s[63];
}

// stage C: add chunk offsets
__global__ __launch_bounds__(1024) void k_scanC(int n) {
    int i = blockIdx.x * blockDim.x + threadIdx.x;
    if (i < n) g_rowstart[i] += g_bsum[blockIdx.x];
}

__global__ void k_fill(const int* __restrict__ ei32, int E) {
    int e = blockIdx.x * blockDim.x + threadIdx.x;
    if (e >= E) return;
    int s = edge_val(ei32, e);
    int d = edge_val(ei32, E + e);
    if (s < 0 || s >= NNODES || d < 0 || d >= NNODES) return;
    int pos = g_rowstart[d] + atomicAdd(&g_cur[d], 1);
    if (pos >= 0 && pos < EMAX) g_csr[pos] = s;
}

// ---------------- GEMM: C[nrows,128] = A[nrows,128] @ W[128,128] ----------------
#define BM 128
#define BN 128
#define BK 32
#define XPAD 36

template <int A_EXT, int DSTSEL>
__global__ __launch_bounds__(256) void k_gemm(const float* __restrict__ Aext,
                                              const float* __restrict__ W,
                                              int nrows) {
    const float* A = A_EXT ? Aext : (const float*)g_h;
    float*       C = DSTSEL ? g_xr : g_xl;

    __shared__ float xs[BM][XPAD];   // [m][k] (padded; row stride 144B, 16B-aligned)
    __shared__ float ws[BK][BN];

    int t  = threadIdx.x;
    int tx = t & 15;      // col group: cols tx*8 .. tx*8+7
    int ty = t >> 4;      // row group: rows ty*8 .. ty*8+7
    int row0 = blockIdx.x * BM;

    unsigned long long acc[8][4];
#pragma unroll
    for (int i = 0; i < 8; i++)
#pragma unroll
        for (int j = 0; j < 4; j++) acc[i][j] = 0ULL;

    for (int k0 = 0; k0 < F; k0 += BK) {
#pragma unroll
        for (int i = 0; i < 4; i++) {
            int f  = t + i * 256;
            int r  = f >> 3;
            int c4 = f & 7;
            float4 v = make_float4(0.f, 0.f, 0.f, 0.f);
            int gr = row0 + r;
            if (gr < nrows) v = *(const float4*)(A + gr * F + k0 + c4 * 4);
            *(float4*)&xs[r][c4 * 4] = v;
        }
#pragma unroll
        for (int i = 0; i < 4; i++) {
            int f  = t + i * 256;
            int r  = f >> 5;
            int c4 = f & 31;
            *(float4*)&ws[r][c4 * 4] = *(const float4*)(W + (k0 + r) * F + c4 * 4);
        }
        __syncthreads();

#pragma unroll
        for (int kk = 0; kk < BK; kk++) {
            unsigned long long xx[8];
#pragma unroll
            for (int i = 0; i < 8; i++) xx[i] = pack2(xs[ty * 8 + i][kk]);
            unsigned long long wv[4];
            const unsigned long long* wp =
                (const unsigned long long*)&ws[kk][tx * 8];
#pragma unroll
            for (int j = 0; j < 4; j++) wv[j] = wp[j];
#pragma unroll
            for (int i = 0; i < 8; i++)
#pragma unroll
                for (int j = 0; j < 4; j++) ffma2(acc[i][j], xx[i], wv[j]);
        }
        __syncthreads();
    }

#pragma unroll
    for (int i = 0; i < 8; i++) {
        int gr = row0 + ty * 8 + i;
        if (gr < nrows) {
            float2* op = (float2*)(C + gr * F + tx * 8);
#pragma unroll
            for (int j = 0; j < 4; j++) op[j] = unpack2(acc[i][j]);
        }
    }
}

// ---------------- fused online-softmax aggregation ----------------
template <int RW, bool RELU, int OUT_EXT>
__global__ __launch_bounds__(256) void k_agg(const float* __restrict__ att,
                                             const float* __restrict__ bias,
                                             float* __restrict__ outext) {
    const float* xl = g_xl;
    const float* xr = g_xr;
    float* out = OUT_EXT ? outext : g_h;

    int gw   = (blockIdx.x * blockDim.x + threadIdx.x) >> 5;
    int lane = threadIdx.x & 31;
    if (gw >= NNODES) return;
    int i = gw;
    int c = lane * 4;

    float4 xr4 = *(const float4*)(xr + i * F + c);
    float4 a4  = *(const float4*)(att + c);
    float4 b4  = *(const float4*)(bias + c);

    float4 xc = *(const float4*)(xl + i * F + c);   // self loop

    auto alpha_of = [&](const float4& v) -> float {
        float e0 = v.x + xr4.x; e0 = e0 > 0.f ? e0 : NEG * e0;
        float e1 = v.y + xr4.y; e1 = e1 > 0.f ? e1 : NEG * e1;
        float e2 = v.z + xr4.z; e2 = e2 > 0.f ? e2 : NEG * e2;
        float e3 = v.w + xr4.w; e3 = e3 > 0.f ? e3 : NEG * e3;
        float p = a4.x * e0 + a4.y * e1 + a4.z * e2 + a4.w * e3;
#pragma unroll
        for (int o = 1; o < RW; o <<= 1)
            p += __shfl_xor_sync(0xffffffffu, p, o);
        return p;
    };

    float  m    = alpha_of(xc);
    float  dsum = 1.f;
    float4 acc  = xc;

    int beg = g_rowstart[i], end = g_rowstart[i + 1];
    float4 xn = make_float4(0.f, 0.f, 0.f, 0.f);
    if (beg < end) {
        int j = g_csr[beg];
        xn = *(const float4*)(xl + j * F + c);
    }
    for (int e = beg; e < end; e++) {
        float4 cur = xn;
        if (e + 1 < end) {
            int j2 = g_csr[e + 1];
            xn = *(const float4*)(xl + j2 * F + c);
        }
        float p  = alpha_of(cur);
        float mn = fmaxf(m, p);
        float corr = __expf(m - mn);
        float w    = __expf(p - mn);
        dsum = dsum * corr + w;
        acc.x = acc.x * corr + w * cur.x;
        acc.y = acc.y * corr + w * cur.y;
        acc.z = acc.z * corr + w * cur.z;
        acc.w = acc.w * corr + w * cur.w;
        m = mn;
    }

    float inv = 1.0f / dsum;
    float4 o;
    o.x = acc.x * inv + b4.x;
    o.y = acc.y * inv + b4.y;
    o.z = acc.z * inv + b4.z;
    o.w = acc.w * inv + b4.w;
    if (RELU) {
        o.x = fmaxf(o.x, 0.f);
        o.y = fmaxf(o.y, 0.f);
        o.z = fmaxf(o.z, 0.f);
        o.w = fmaxf(o.w, 0.f);
    }
    *(float4*)(out + i * F + c) = o;
}

// ---------------- launch (kernel launches ONLY — graph-capture safe) ----------------
extern "C" void kernel_launch(void* const* d_in, const int* in_sizes, int n_in,
                              void* d_out, int out_size) {
    const float* x    = (const float*)d_in[0];
    const int*   ei32 = (const int*)d_in[1];
    const float* Wl1  = (const float*)d_in[2];
    const float* Wr1  = (const float*)d_in[3];
    const float* att1 = (const float*)d_in[4];
    const float* b1   = (const float*)d_in[5];
    const float* Wl2  = (const float*)d_in[6];
    const float* Wr2  = (const float*)d_in[7];
    const float* att2 = (const float*)d_in[8];
    const float* b2   = (const float*)d_in[9];
    float*       out  = (float*)d_out;

    // Edge count: robust to int64-as-int32 staging (4E ints) vs int32 (2E ints).
    int cnt = in_sizes[1];
    int E   = (cnt / 2 > EMAX) ? cnt / 4 : cnt / 2;
    if (E > EMAX) E = EMAX;

    int eb = (E + 255) / 256;
    int gb = (NNODES + BM - 1) / BM;          // 391
    int ab = (NNODES * 32 + 255) / 256;       // 6250

    k_zero<<<(NNODES + 255) / 256, 256>>>(ei32);
    k_count<<<eb, 256>>>(ei32, E);
    k_scanA<<<NB_SCAN, 1024>>>(NNODES);
    k_scanB<<<1, 64>>>(NB_SCAN, NNODES);
    k_scanC<<<NB_SCAN, 1024>>>(NNODES);
    k_fill<<<eb, 256>>>(ei32, E);

    // layer 1: xl = x@Wl1, xr = x@Wr1, h = agg+relu
    k_gemm<1, 0><<<gb, 256>>>(x, Wl1, NNODES);
    k_gemm<1, 1><<<gb, 256>>>(x, Wr1, NNODES);
    k_agg<8, true, 0><<<ab, 256>>>(att1, b1, out);

    // layer 2: xl = h@Wl2, xr = h@Wr2, out = agg
    k_gemm<0, 0><<<gb, 256>>>(nullptr, Wl2, NNODES);
    k_gemm<0, 1><<<gb, 256>>>(nullptr, Wr2, NNODES);
    k_agg<32, false, 1><<<ab, 256>>>(att2, b2, out);
}

// round 6
// speedup vs baseline: 1.6466x; 1.4172x over previous
#include <cuda_runtime.h>
#include <cuda_bf16.h>
#include <cstdint>

#define NNODES 50000
#define F 128
#define EMAX 800000
#define NEG 0.2f
#define NB_SCAN ((NNODES + 1023) / 1024)   // 49

// ---------------- scratch (no allocation allowed) ----------------
__device__ int   g_deg[NNODES];
__device__ int   g_cur[NNODES];
__device__ int   g_rowstart[NNODES + 1];
__device__ int   g_bsum[64];
__device__ int   g_csr[EMAX];
__device__ int   g_is64;
__device__ float g_xl[NNODES * F];
__device__ float g_xr[NNODES * F];
__device__ float g_h[NNODES * F];

// ---------------- zero + edge layout detection ----------------
__global__ void k_zero(const int* __restrict__ ei32) {
    int i = blockIdx.x * blockDim.x + threadIdx.x;
    if (i < NNODES) { g_deg[i] = 0; g_cur[i] = 0; }
    if (i == 0) {
        int z = 0;
#pragma unroll
        for (int k = 0; k < 8; k++) z |= ei32[2 * k + 1];
        g_is64 = (z == 0) ? 1 : 0;
    }
}

__device__ __forceinline__ int edge_val(const int* __restrict__ ei32, int idx) {
    return g_is64 ? ei32[2 * idx] : ei32[idx];
}

// ---------------- CSR construction ----------------
__global__ void k_count(const int* __restrict__ ei32, int E) {
    int e = blockIdx.x * blockDim.x + threadIdx.x;
    if (e >= E) return;
    int s = edge_val(ei32, e);
    int d = edge_val(ei32, E + e);
    if (s >= 0 && s < NNODES && d >= 0 && d < NNODES) atomicAdd(&g_deg[d], 1);
}

__global__ __launch_bounds__(1024) void k_scanA(int n) {
    __shared__ int wsum[32];
    int b = blockIdx.x, t = threadIdx.x;
    int lane = t & 31, w = t >> 5;
    int idx = b * 1024 + t;
    int v = (idx < n) ? g_deg[idx] : 0;
    int s = v;
#pragma unroll
    for (int o = 1; o < 32; o <<= 1) {
        int u = __shfl_up_sync(0xffffffffu, s, o);
        if (lane >= o) s += u;
    }
    if (lane == 31) wsum[w] = s;
    __syncthreads();
    if (w == 0) {
        int ws = wsum[lane];
#pragma unroll
        for (int o = 1; o < 32; o <<= 1) {
            int u = __shfl_up_sync(0xffffffffu, ws, o);
            if (lane >= o) ws += u;
        }
        wsum[lane] = ws;
    }
    __syncthreads();
    int excl = s - v + (w > 0 ? wsum[w - 1] : 0);
    if (idx < n) g_rowstart[idx] = excl;
    if (t == 1023) g_bsum[b] = wsum[31];
}

__global__ void k_scanB(int nb, int n) {
    __shared__ int s[64];
    int t = threadIdx.x;
    int v = (t < nb) ? g_bsum[t] : 0;
    s[t] = v;
    __syncthreads();
#pragma unroll
    for (int off = 1; off < 64; off <<= 1) {
        int a = (t >= off) ? s[t - off] : 0;
        __syncthreads();
        s[t] += a;
        __syncthreads();
    }
    if (t < nb) g_bsum[t] = s[t] - v;
    if (t == 63) g_rowstart[n] = s[63];
}

__global__ __launch_bounds__(1024) void k_scanC(int n) {
    int i = blockIdx.x * blockDim.x + threadIdx.x;
    if (i < n) g_rowstart[i] += g_bsum[blockIdx.x];
}

__global__ void k_fill(const int* __restrict__ ei32, int E) {
    int e = blockIdx.x * blockDim.x + threadIdx.x;
    if (e >= E) return;
    int s = edge_val(ei32, e);
    int d = edge_val(ei32, E + e);
    if (s < 0 || s >= NNODES || d < 0 || d >= NNODES) return;
    int pos = g_rowstart[d] + atomicAdd(&g_cur[d], 1);
    if (pos >= 0 && pos < EMAX) g_csr[pos] = s;
}

// ---------------- bf16 split helpers ----------------
__device__ __forceinline__ uint32_t pack_bf16x2(float lo, float hi) {
    uint32_t r;
    asm("cvt.rn.bf16x2.f32 %0, %1, %2;" : "=r"(r) : "f"(hi), "f"(lo));
    return r;
}
__device__ __forceinline__ void split_pair(float v0, float v1,
                                           uint32_t& hp, uint32_t& lp) {
    hp = pack_bf16x2(v0, v1);
    float h0 = __uint_as_float(hp << 16);
    float h1 = __uint_as_float(hp & 0xffff0000u);
    lp = pack_bf16x2(v0 - h0, v1 - h1);
}

__device__ __forceinline__ void mma_bf16(float* d, const uint32_t* a,
                                         uint32_t b0, uint32_t b1) {
    asm volatile(
        "mma.sync.aligned.m16n8k16.row.col.f32.bf16.bf16.f32 "
        "{%0,%1,%2,%3}, {%4,%5,%6,%7}, {%8,%9}, {%0,%1,%2,%3};"
        : "+f"(d[0]), "+f"(d[1]), "+f"(d[2]), "+f"(d[3])
        : "r"(a[0]), "r"(a[1]), "r"(a[2]), "r"(a[3]), "r"(b0), "r"(b1));
}

// ---------------- mma.sync bf16-split GEMM: C[nrows,128] = A[nrows,128] @ W[128,128]
// block = 128 rows x 128 cols; 8 warps in 4x2 (rows x cols); warp tile 32x64.
// k-chunks of 16 (8 bf16 pairs). smem arrays padded to stride 12 words.
#define SSTR 12
template <int A_EXT, int DSTSEL>
__global__ __launch_bounds__(256) void k_gemm_mma(const float* __restrict__ Aext,
                                                  const float* __restrict__ W,
                                                  int nrows) {
    const float* A = A_EXT ? Aext : (const float*)g_h;
    float*       C = DSTSEL ? g_xr : g_xl;

    __shared__ uint32_t As_hi[128 * SSTR];
    __shared__ uint32_t As_lo[128 * SSTR];
    __shared__ uint32_t Bs_hi[128 * SSTR];
    __shared__ uint32_t Bs_lo[128 * SSTR];

    int t    = threadIdx.x;
    int warp = t >> 5, lane = t & 31;
    int wr = (warp & 3) * 32;      // warp row base
    int wn = (warp >> 2) * 64;     // warp col base
    int fr = lane >> 2, fk = lane & 3;
    int row0 = blockIdx.x * 128;

    float acc[2][8][4];
#pragma unroll
    for (int mt = 0; mt < 2; mt++)
#pragma unroll
        for (int nt = 0; nt < 8; nt++)
#pragma unroll
            for (int q = 0; q < 4; q++) acc[mt][nt][q] = 0.f;

    for (int k0 = 0; k0 < F; k0 += 16) {
        // stage A chunk: 128 rows x 8 pairs
#pragma unroll
        for (int i = 0; i < 4; i++) {
            int p  = t + i * 256;
            int r  = p >> 3, kp = p & 7;
            int gr = row0 + r;
            float2 v = (gr < nrows)
                           ? *(const float2*)(A + gr * F + k0 + kp * 2)
                           : make_float2(0.f, 0.f);
            uint32_t hp, lp;
            split_pair(v.x, v.y, hp, lp);
            As_hi[r * SSTR + kp] = hp;
            As_lo[r * SSTR + kp] = lp;
        }
        // stage B chunk: W[k0+2kp..+1][n] for n=0..127, kp=0..7 (coalesced over n)
#pragma unroll
        for (int i = 0; i < 4; i++) {
            int p = t + i * 256;
            int n = p & 127, kp = p >> 7;      // i contributes kp pairs 0..7 over 4 iters? no:
            // p in [0,1024): use n = p % 128, kp = p / 128
            float w0 = W[(k0 + kp * 2) * F + n];
            float w1 = W[(k0 + kp * 2 + 1) * F + n];
            uint32_t hp, lp;
            split_pair(w0, w1, hp, lp);
            Bs_hi[n * SSTR + kp] = hp;
            Bs_lo[n * SSTR + kp] = lp;
        }
        __syncthreads();

        // A fragments (2 m-tiles)
        uint32_t ah[2][4], al[2][4];
#pragma unroll
        for (int mt = 0; mt < 2; mt++) {
            int rb = wr + mt * 16;
            ah[mt][0] = As_hi[(rb + fr) * SSTR + fk];
            ah[mt][1] = As_hi[(rb + fr + 8) * SSTR + fk];
            ah[mt][2] = As_hi[(rb + fr) * SSTR + fk + 4];
            ah[mt][3] = As_hi[(rb + fr + 8) * SSTR + fk + 4];
            al[mt][0] = As_lo[(rb + fr) * SSTR + fk];
            al[mt][1] = As_lo[(rb + fr + 8) * SSTR + fk];
            al[mt][2] = As_lo[(rb + fr) * SSTR + fk + 4];
            al[mt][3] = As_lo[(rb + fr + 8) * SSTR + fk + 4];
        }
#pragma unroll
        for (int nt = 0; nt < 8; nt++) {
            int nb = wn + nt * 8;
            uint32_t bh0 = Bs_hi[(nb + fr) * SSTR + fk];
            uint32_t bh1 = Bs_hi[(nb + fr) * SSTR + fk + 4];
            uint32_t bl0 = Bs_lo[(nb + fr) * SSTR + fk];
            uint32_t bl1 = Bs_lo[(nb + fr) * SSTR + fk + 4];
#pragma unroll
            for (int mt = 0; mt < 2; mt++) {
                mma_bf16(acc[mt][nt], ah[mt], bh0, bh1);
                mma_bf16(acc[mt][nt], ah[mt], bl0, bl1);
                mma_bf16(acc[mt][nt], al[mt], bh0, bh1);
            }
        }
        __syncthreads();
    }

    // epilogue: d0,d1 -> (row fr, cols 2fk,2fk+1); d2,d3 -> row fr+8
#pragma unroll
    for (int mt = 0; mt < 2; mt++) {
#pragma unroll
        for (int nt = 0; nt < 8; nt++) {
            int col = wn + nt * 8 + fk * 2;
            int r1  = row0 + wr + mt * 16 + fr;
            int r2  = r1 + 8;
            if (r1 < nrows)
                *(float2*)(C + r1 * F + col) =
                    make_float2(acc[mt][nt][0], acc[mt][nt][1]);
            if (r2 < nrows)
                *(float2*)(C + r2 * F + col) =
                    make_float2(acc[mt][nt][2], acc[mt][nt][3]);
        }
    }
}

// ---------------- fused online-softmax aggregation ----------------
template <int RW, bool RELU, int OUT_EXT>
__global__ __launch_bounds__(256) void k_agg(const float* __restrict__ att,
                                             const float* __restrict__ bias,
                                             float* __restrict__ outext) {
    const float* xl = g_xl;
    const float* xr = g_xr;
    float* out = OUT_EXT ? outext : g_h;

    int gw   = (blockIdx.x * blockDim.x + threadIdx.x) >> 5;
    int lane = threadIdx.x & 31;
    if (gw >= NNODES) return;
    int i = gw;
    int c = lane * 4;

    float4 xr4 = *(const float4*)(xr + i * F + c);
    float4 a4  = *(const float4*)(att + c);
    float4 b4  = *(const float4*)(bias + c);

    float4 xc = *(const float4*)(xl + i * F + c);   // self loop

    auto alpha_of = [&](const float4& v) -> float {
        float e0 = v.x + xr4.x; e0 = e0 > 0.f ? e0 : NEG * e0;
        float e1 = v.y + xr4.y; e1 = e1 > 0.f ? e1 : NEG * e1;
        float e2 = v.z + xr4.z; e2 = e2 > 0.f ? e2 : NEG * e2;
        float e3 = v.w + xr4.w; e3 = e3 > 0.f ? e3 : NEG * e3;
        float p = a4.x * e0 + a4.y * e1 + a4.z * e2 + a4.w * e3;
#pragma unroll
        for (int o = 1; o < RW; o <<= 1)
            p += __shfl_xor_sync(0xffffffffu, p, o);
        return p;
    };

    float  m    = alpha_of(xc);
    float  dsum = 1.f;
    float4 acc  = xc;

    int beg = g_rowstart[i], end = g_rowstart[i + 1];
    float4 xn = make_float4(0.f, 0.f, 0.f, 0.f);
    if (beg < end) {
        int j = g_csr[beg];
        xn = *(const float4*)(xl + j * F + c);
    }
    for (int e = beg; e < end; e++) {
        float4 cur = xn;
        if (e + 1 < end) {
            int j2 = g_csr[e + 1];
            xn = *(const float4*)(xl + j2 * F + c);
        }
        float p  = alpha_of(cur);
        float mn = fmaxf(m, p);
        float corr = __expf(m - mn);
        float w    = __expf(p - mn);
        dsum = dsum * corr + w;
        acc.x = acc.x * corr + w * cur.x;
        acc.y = acc.y * corr + w * cur.y;
        acc.z = acc.z * corr + w * cur.z;
        acc.w = acc.w * corr + w * cur.w;
        m = mn;
    }

    float inv = 1.0f / dsum;
    float4 o;
    o.x = acc.x * inv + b4.x;
    o.y = acc.y * inv + b4.y;
    o.z = acc.z * inv + b4.z;
    o.w = acc.w * inv + b4.w;
    if (RELU) {
        o.x = fmaxf(o.x, 0.f);
        o.y = fmaxf(o.y, 0.f);
        o.z = fmaxf(o.z, 0.f);
        o.w = fmaxf(o.w, 0.f);
    }
    *(float4*)(out + i * F + c) = o;
}

// ---------------- launch (kernel launches ONLY) ----------------
extern "C" void kernel_launch(void* const* d_in, const int* in_sizes, int n_in,
                              void* d_out, int out_size) {
    const float* x    = (const float*)d_in[0];
    const int*   ei32 = (const int*)d_in[1];
    const float* Wl1  = (const float*)d_in[2];
    const float* Wr1  = (const float*)d_in[3];
    const float* att1 = (const float*)d_in[4];
    const float* b1   = (const float*)d_in[5];
    const float* Wl2  = (const float*)d_in[6];
    const float* Wr2  = (const float*)d_in[7];
    const float* att2 = (const float*)d_in[8];
    const float* b2   = (const float*)d_in[9];
    float*       out  = (float*)d_out;

    int cnt = in_sizes[1];
    int E   = (cnt / 2 > EMAX) ? cnt / 4 : cnt / 2;
    if (E > EMAX) E = EMAX;

    int eb = (E + 255) / 256;
    int gb = (NNODES + 127) / 128;            // 391
    int ab = (NNODES * 32 + 255) / 256;       // 6250

    k_zero<<<(NNODES + 255) / 256, 256>>>(ei32);
    k_count<<<eb, 256>>>(ei32, E);
    k_scanA<<<NB_SCAN, 1024>>>(NNODES);
    k_scanB<<<1, 64>>>(NB_SCAN, NNODES);
    k_scanC<<<NB_SCAN, 1024>>>(NNODES);
    k_fill<<<eb, 256>>>(ei32, E);

    // layer 1
    k_gemm_mma<1, 0><<<gb, 256>>>(x, Wl1, NNODES);
    k_gemm_mma<1, 1><<<gb, 256>>>(x, Wr1, NNODES);
    k_agg<8, true, 0><<<ab, 256>>>(att1, b1, out);

    // layer 2
    k_gemm_mma<0, 0><<<gb, 256>>>(nullptr, Wl2, NNODES);
    k_gemm_mma<0, 1><<<gb, 256>>>(nullptr, Wr2, NNODES);
    k_agg<32, false, 1><<<ab, 256>>>(att2, b2, out);
}

// round 7
// speedup vs baseline: 1.6532x; 1.0040x over previous
#include <cuda_runtime.h>
#include <cuda_bf16.h>
#include <cstdint>

#define NNODES 50000
#define F 128
#define EMAX 800000
#define NEG 0.2f
#define NB_SCAN ((NNODES + 1023) / 1024)   // 49

// ---------------- scratch (no allocation allowed) ----------------
__device__ int   g_deg[NNODES];
__device__ int   g_cur[NNODES];
__device__ int   g_rowstart[NNODES + 1];
__device__ int   g_bsum[64];
__device__ int   g_csr[EMAX];
__device__ int   g_is64;
__device__ float g_xl[NNODES * F];
__device__ float g_xr[NNODES * F];
__device__ float g_h[NNODES * F];

// ---------------- zero + edge layout detection ----------------
__global__ void k_zero(const int* __restrict__ ei32) {
    int i = blockIdx.x * blockDim.x + threadIdx.x;
    if (i < NNODES) { g_deg[i] = 0; g_cur[i] = 0; }
    if (i == 0) {
        int z = 0;
#pragma unroll
        for (int k = 0; k < 8; k++) z |= ei32[2 * k + 1];
        g_is64 = (z == 0) ? 1 : 0;
    }
}

__device__ __forceinline__ int edge_val(const int* __restrict__ ei32, int idx) {
    return g_is64 ? ei32[2 * idx] : ei32[idx];
}

// ---------------- CSR construction ----------------
__global__ void k_count(const int* __restrict__ ei32, int E) {
    int e = blockIdx.x * blockDim.x + threadIdx.x;
    if (e >= E) return;
    int s = edge_val(ei32, e);
    int d = edge_val(ei32, E + e);
    if (s >= 0 && s < NNODES && d >= 0 && d < NNODES) atomicAdd(&g_deg[d], 1);
}

__global__ __launch_bounds__(1024) void k_scanA(int n) {
    __shared__ int wsum[32];
    int b = blockIdx.x, t = threadIdx.x;
    int lane = t & 31, w = t >> 5;
    int idx = b * 1024 + t;
    int v = (idx < n) ? g_deg[idx] : 0;
    int s = v;
#pragma unroll
    for (int o = 1; o < 32; o <<= 1) {
        int u = __shfl_up_sync(0xffffffffu, s, o);
        if (lane >= o) s += u;
    }
    if (lane == 31) wsum[w] = s;
    __syncthreads();
    if (w == 0) {
        int ws = wsum[lane];
#pragma unroll
        for (int o = 1; o < 32; o <<= 1) {
            int u = __shfl_up_sync(0xffffffffu, ws, o);
            if (lane >= o) ws += u;
        }
        wsum[lane] = ws;
    }
    __syncthreads();
    int excl = s - v + (w > 0 ? wsum[w - 1] : 0);
    if (idx < n) g_rowstart[idx] = excl;
    if (t == 1023) g_bsum[b] = wsum[31];
}

__global__ void k_scanB(int nb, int n) {
    __shared__ int s[64];
    int t = threadIdx.x;
    int v = (t < nb) ? g_bsum[t] : 0;
    s[t] = v;
    __syncthreads();
#pragma unroll
    for (int off = 1; off < 64; off <<= 1) {
        int a = (t >= off) ? s[t - off] : 0;
        __syncthreads();
        s[t] += a;
        __syncthreads();
    }
    if (t < nb) g_bsum[t] = s[t] - v;
    if (t == 63) g_rowstart[n] = s[63];
}

__global__ __launch_bounds__(1024) void k_scanC(int n) {
    int i = blockIdx.x * blockDim.x + threadIdx.x;
    if (i < n) g_rowstart[i] += g_bsum[blockIdx.x];
}

__global__ void k_fill(const int* __restrict__ ei32, int E) {
    int e = blockIdx.x * blockDim.x + threadIdx.x;
    if (e >= E) return;
    int s = edge_val(ei32, e);
    int d = edge_val(ei32, E + e);
    if (s < 0 || s >= NNODES || d < 0 || d >= NNODES) return;
    int pos = g_rowstart[d] + atomicAdd(&g_cur[d], 1);
    if (pos >= 0 && pos < EMAX) g_csr[pos] = s;
}

// ---------------- bf16 split helpers ----------------
__device__ __forceinline__ uint32_t pack_bf16x2(float lo, float hi) {
    uint32_t r;
    asm("cvt.rn.bf16x2.f32 %0, %1, %2;" : "=r"(r) : "f"(hi), "f"(lo));
    return r;
}
__device__ __forceinline__ void split_pair(float v0, float v1,
                                           uint32_t& hp, uint32_t& lp) {
    hp = pack_bf16x2(v0, v1);
    float h0 = __uint_as_float(hp << 16);
    float h1 = __uint_as_float(hp & 0xffff0000u);
    lp = pack_bf16x2(v0 - h0, v1 - h1);
}

__device__ __forceinline__ void mma_bf16(float* d, const uint32_t* a,
                                         uint32_t b0, uint32_t b1) {
    asm volatile(
        "mma.sync.aligned.m16n8k16.row.col.f32.bf16.bf16.f32 "
        "{%0,%1,%2,%3}, {%4,%5,%6,%7}, {%8,%9}, {%0,%1,%2,%3};"
        : "+f"(d[0]), "+f"(d[1]), "+f"(d[2]), "+f"(d[3])
        : "r"(a[0]), "r"(a[1]), "r"(a[2]), "r"(a[3]), "r"(b0), "r"(b1));
}

// ---------------- dual-output mma.sync GEMM ----------------
// xl[nrows,128] = A @ Wl ; xr[nrows,128] = A @ Wr, one block = 128 rows.
// 512 threads: warps 0-7 -> xl, warps 8-15 -> xr; A staged/split once.
#define SSTR 12
template <int A_EXT>
__global__ __launch_bounds__(512) void k_gemm_dual(const float* __restrict__ Aext,
                                                   const float* __restrict__ Wl,
                                                   const float* __restrict__ Wr,
                                                   int nrows) {
    const float* A = A_EXT ? Aext : (const float*)g_h;

    __shared__ uint32_t As_hi[128 * SSTR];
    __shared__ uint32_t As_lo[128 * SSTR];
    __shared__ uint32_t Bs_hi[2][128 * SSTR];
    __shared__ uint32_t Bs_lo[2][128 * SSTR];

    int t    = threadIdx.x;
    int warp = t >> 5, lane = t & 31;
    int half = warp >> 3;          // 0 -> xl, 1 -> xr
    int w    = warp & 7;
    int wr = (w & 3) * 32;         // warp row base
    int wn = (w >> 2) * 64;        // warp col base
    int fr = lane >> 2, fk = lane & 3;
    int row0 = blockIdx.x * 128;
    const float* W = half ? Wr : Wl;
    float*       C = half ? g_xr : g_xl;

    float acc[2][8][4];
#pragma unroll
    for (int mt = 0; mt < 2; mt++)
#pragma unroll
        for (int nt = 0; nt < 8; nt++)
#pragma unroll
            for (int q = 0; q < 4; q++) acc[mt][nt][q] = 0.f;

    for (int k0 = 0; k0 < F; k0 += 16) {
        // stage A chunk once: 128 rows x 8 pairs = 1024 entries, 2 iters
#pragma unroll
        for (int i = 0; i < 2; i++) {
            int p  = t + i * 512;
            int r  = p >> 3, kp = p & 7;
            int gr = row0 + r;
            float2 v = (gr < nrows)
                           ? *(const float2*)(A + gr * F + k0 + kp * 2)
                           : make_float2(0.f, 0.f);
            uint32_t hp, lp;
            split_pair(v.x, v.y, hp, lp);
            As_hi[r * SSTR + kp] = hp;
            As_lo[r * SSTR + kp] = lp;
        }
        // stage this half's B chunk: 1024 entries, 2 iters (n coalesced)
#pragma unroll
        for (int i = 0; i < 2; i++) {
            int p = (t & 255) + i * 256;
            int n = p & 127, kp = p >> 7;
            // each half staged by its own 256 threads over 2 iters covers kp 0..7?
            // (t&255) in [0,256) + i*256 -> p in [0,512): kp in 0..3 only. Use 4 iters of 128:
            (void)n; (void)kp;
        }
        // correct B staging: 8 warps of this half cover 1024 entries in 4 iters of 256
        {
            int ht = (t & 255);            // thread id within half (0..255)
#pragma unroll
            for (int i = 0; i < 4; i++) {
                int p = ht + i * 256;
                int n = p & 127, kp = p >> 7;
                float w0 = W[(k0 + kp * 2) * F + n];
                float w1 = W[(k0 + kp * 2 + 1) * F + n];
                uint32_t hp, lp;
                split_pair(w0, w1, hp, lp);
                Bs_hi[half][n * SSTR + kp] = hp;
                Bs_lo[half][n * SSTR + kp] = lp;
            }
        }
        __syncthreads();

        uint32_t ah[2][4], al[2][4];
#pragma unroll
        for (int mt = 0; mt < 2; mt++) {
            int rb = wr + mt * 16;
            ah[mt][0] = As_hi[(rb + fr) * SSTR + fk];
            ah[mt][1] = As_hi[(rb + fr + 8) * SSTR + fk];
            ah[mt][2] = As_hi[(rb + fr) * SSTR + fk + 4];
            ah[mt][3] = As_hi[(rb + fr + 8) * SSTR + fk + 4];
            al[mt][0] = As_lo[(rb + fr) * SSTR + fk];
            al[mt][1] = As_lo[(rb + fr + 8) * SSTR + fk];
            al[mt][2] = As_lo[(rb + fr) * SSTR + fk + 4];
            al[mt][3] = As_lo[(rb + fr + 8) * SSTR + fk + 4];
        }
#pragma unroll
        for (int nt = 0; nt < 8; nt++) {
            int nb = wn + nt * 8;
            uint32_t bh0 = Bs_hi[half][(nb + fr) * SSTR + fk];
            uint32_t bh1 = Bs_hi[half][(nb + fr) * SSTR + fk + 4];
            uint32_t bl0 = Bs_lo[half][(nb + fr) * SSTR + fk];
            uint32_t bl1 = Bs_lo[half][(nb + fr) * SSTR + fk + 4];
#pragma unroll
            for (int mt = 0; mt < 2; mt++) {
                mma_bf16(acc[mt][nt], ah[mt], bh0, bh1);
                mma_bf16(acc[mt][nt], ah[mt], bl0, bl1);
                mma_bf16(acc[mt][nt], al[mt], bh0, bh1);
            }
        }
        __syncthreads();
    }

#pragma unroll
    for (int mt = 0; mt < 2; mt++) {
#pragma unroll
        for (int nt = 0; nt < 8; nt++) {
            int col = wn + nt * 8 + fk * 2;
            int r1  = row0 + wr + mt * 16 + fr;
            int r2  = r1 + 8;
            if (r1 < nrows)
                *(float2*)(C + r1 * F + col) =
                    make_float2(acc[mt][nt][0], acc[mt][nt][1]);
            if (r2 < nrows)
                *(float2*)(C + r2 * F + col) =
                    make_float2(acc[mt][nt][2], acc[mt][nt][3]);
        }
    }
}

// ---------------- fused online-softmax aggregation ----------------
template <int RW, bool RELU, int OUT_EXT>
__global__ __launch_bounds__(256) void k_agg(const float* __restrict__ att,
                                             const float* __restrict__ bias,
                                             float* __restrict__ outext) {
    const float* xl = g_xl;
    const float* xr = g_xr;
    float* out = OUT_EXT ? outext : g_h;

    int gw   = (blockIdx.x * blockDim.x + threadIdx.x) >> 5;
    int lane = threadIdx.x & 31;
    if (gw >= NNODES) return;
    int i = gw;
    int c = lane * 4;

    float4 xr4 = *(const float4*)(xr + i * F + c);
    float4 a4  = *(const float4*)(att + c);
    float4 b4  = *(const float4*)(bias + c);

    float4 xc = *(const float4*)(xl + i * F + c);   // self loop

    auto alpha_of = [&](const float4& v) -> float {
        float e0 = v.x + xr4.x; e0 = e0 > 0.f ? e0 : NEG * e0;
        float e1 = v.y + xr4.y; e1 = e1 > 0.f ? e1 : NEG * e1;
        float e2 = v.z + xr4.z; e2 = e2 > 0.f ? e2 : NEG * e2;
        float e3 = v.w + xr4.w; e3 = e3 > 0.f ? e3 : NEG * e3;
        float p = a4.x * e0 + a4.y * e1 + a4.z * e2 + a4.w * e3;
#pragma unroll
        for (int o = 1; o < RW; o <<= 1)
            p += __shfl_xor_sync(0xffffffffu, p, o);
        return p;
    };

    float  m    = alpha_of(xc);
    float  dsum = 1.f;
    float4 acc  = xc;

    int beg = g_rowstart[i], end = g_rowstart[i + 1];
    float4 xn = make_float4(0.f, 0.f, 0.f, 0.f);
    if (beg < end) {
        int j = g_csr[beg];
        xn = *(const float4*)(xl + j * F + c);
    }
    for (int e = beg; e < end; e++) {
        float4 cur = xn;
        if (e + 1 < end) {
            int j2 = g_csr[e + 1];
            xn = *(const float4*)(xl + j2 * F + c);
        }
        float p  = alpha_of(cur);
        float mn = fmaxf(m, p);
        float corr = __expf(m - mn);
        float w    = __expf(p - mn);
        dsum = dsum * corr + w;
        acc.x = acc.x * corr + w * cur.x;
        acc.y = acc.y * corr + w * cur.y;
        acc.z = acc.z * corr + w * cur.z;
        acc.w = acc.w * corr + w * cur.w;
        m = mn;
    }

    float inv = 1.0f / dsum;
    float4 o;
    o.x = acc.x * inv + b4.x;
    o.y = acc.y * inv + b4.y;
    o.z = acc.z * inv + b4.z;
    o.w = acc.w * inv + b4.w;
    if (RELU) {
        o.x = fmaxf(o.x, 0.f);
        o.y = fmaxf(o.y, 0.f);
        o.z = fmaxf(o.z, 0.f);
        o.w = fmaxf(o.w, 0.f);
    }
    *(float4*)(out + i * F + c) = o;
}

// ---------------- launch (kernel launches ONLY) ----------------
extern "C" void kernel_launch(void* const* d_in, const int* in_sizes, int n_in,
                              void* d_out, int out_size) {
    const float* x    = (const float*)d_in[0];
    const int*   ei32 = (const int*)d_in[1];
    const float* Wl1  = (const float*)d_in[2];
    const float* Wr1  = (const float*)d_in[3];
    const float* att1 = (const float*)d_in[4];
    const float* b1   = (const float*)d_in[5];
    const float* Wl2  = (const float*)d_in[6];
    const float* Wr2  = (const float*)d_in[7];
    const float* att2 = (const float*)d_in[8];
    const float* b2   = (const float*)d_in[9];
    float*       out  = (float*)d_out;

    int cnt = in_sizes[1];
    int E   = (cnt / 2 > EMAX) ? cnt / 4 : cnt / 2;
    if (E > EMAX) E = EMAX;

    int eb = (E + 255) / 256;
    int gb = (NNODES + 127) / 128;            // 391
    int ab = (NNODES * 32 + 255) / 256;       // 6250

    k_zero<<<(NNODES + 255) / 256, 256>>>(ei32);
    k_count<<<eb, 256>>>(ei32, E);
    k_scanA<<<NB_SCAN, 1024>>>(NNODES);
    k_scanB<<<1, 64>>>(NB_SCAN, NNODES);
    k_scanC<<<NB_SCAN, 1024>>>(NNODES);
    k_fill<<<eb, 256>>>(ei32, E);

    // layer 1
    k_gemm_dual<1><<<gb, 512>>>(x, Wl1, Wr1, NNODES);
    k_agg<8, true, 0><<<ab, 256>>>(att1, b1, out);

    // layer 2
    k_gemm_dual<0><<<gb, 512>>>(nullptr, Wl2, Wr2, NNODES);
    k_agg<32, false, 1><<<ab, 256>>>(att2, b2, out);
}